// round 13
// baseline (speedup 1.0000x reference)
#include <cuda_runtime.h>
#include <cuda_bf16.h>
#include <mma.h>
#include <math.h>
#include <stdint.h>

using namespace nvcuda;

#define BD 4
#define SD 4096
#define HD 32
#define PD 64
#define ND 64
#define BLK 64
#define NCH 64
#define LDS_ 72   // smem tile leading dim (elements)

// Scratch: chunk states [b][h][chunk][n][p]; k2 converts in-place to incoming states
__device__ float g_states[(size_t)BD * HD * NCH * ND * PD];
__device__ float g_atot[BD * HD * NCH];

__device__ __forceinline__ void bsplit(float v, __nv_bfloat16& h, __nv_bfloat16& l) {
  h = __float2bfloat16_rn(v);
  l = __float2bfloat16_rn(v - __bfloat162float(h));
}
__device__ __forceinline__ uint32_t pk(__nv_bfloat16 a, __nv_bfloat16 b) {
  return (uint32_t)__bfloat16_as_ushort(a) | ((uint32_t)__bfloat16_as_ushort(b) << 16);
}
// split 4 floats -> two packed-hi words and two packed-lo words, store to tile
__device__ __forceinline__ void split4_store(__nv_bfloat16* th, __nv_bfloat16* tl,
                                             int row, int cp, float4 v) {
  __nv_bfloat16 h0, l0, h1, l1, h2, l2, h3, l3;
  bsplit(v.x, h0, l0); bsplit(v.y, h1, l1);
  bsplit(v.z, h2, l2); bsplit(v.w, h3, l3);
  *(uint32_t*)&th[row * LDS_ + cp]     = pk(h0, h1);
  *(uint32_t*)&th[row * LDS_ + cp + 2] = pk(h2, h3);
  *(uint32_t*)&tl[row * LDS_ + cp]     = pk(l0, l1);
  *(uint32_t*)&tl[row * LDS_ + cp + 2] = pk(l2, l3);
}

typedef wmma::fragment<wmma::matrix_a, 16, 16, 16, __nv_bfloat16, wmma::row_major> FragAR;
typedef wmma::fragment<wmma::matrix_a, 16, 16, 16, __nv_bfloat16, wmma::col_major> FragAC;
typedef wmma::fragment<wmma::matrix_b, 16, 16, 16, __nv_bfloat16, wmma::row_major> FragBR;
typedef wmma::fragment<wmma::matrix_b, 16, 16, 16, __nv_bfloat16, wmma::col_major> FragBC;
typedef wmma::fragment<wmma::accumulator, 16, 16, 16, float> FragC;

// ---------------------------------------------------------------------------
// Shared cumsum of A over the chunk (64 values) -> s_cum
// ---------------------------------------------------------------------------
__device__ __forceinline__ void chunk_cumsum(const float* Ap, float* s_cum, int tid) {
  if (tid < 64) {
    float v = Ap[(size_t)tid * HD];
#pragma unroll
    for (int o = 1; o < 32; o <<= 1) {
      float t = __shfl_up_sync(0xffffffffu, v, o);
      if ((tid & 31) >= o) v += t;
    }
    s_cum[tid] = v;
  }
  __syncthreads();
  if (tid >= 32 && tid < 64) s_cum[tid] += s_cum[31];
  __syncthreads();
}

// ---------------------------------------------------------------------------
// K1: per (b,h,chunk): states[n][p] = sum_l Bdec[l][n] * X[l][p]
// ---------------------------------------------------------------------------
__global__ __launch_bounds__(256)
void k1_states(const float* __restrict__ A, const float* __restrict__ B,
               const float* __restrict__ X) {
  extern __shared__ char sm1[];
  __nv_bfloat16* sBh = (__nv_bfloat16*)sm1;
  __nv_bfloat16* sBl = sBh + 64 * LDS_;
  __nv_bfloat16* sXh = sBl + 64 * LDS_;
  __nv_bfloat16* sXl = sXh + 64 * LDS_;
  __shared__ float s_cum[BLK];
  __shared__ float s_dec[BLK];
  const int tid = threadIdx.x;
  const int ch = blockIdx.x, h = blockIdx.y, b = blockIdx.z;

  const float* Ap = A + ((size_t)b * SD + (size_t)ch * BLK) * HD + h;
  chunk_cumsum(Ap, s_cum, tid);
  const float total = s_cum[63];
  if (tid < 64) s_dec[tid] = expf(total - s_cum[tid]);
  if (tid == 0) g_atot[((size_t)b * HD + h) * NCH + ch] = total;
  __syncthreads();

  const size_t rowoff = ((size_t)b * SD + (size_t)ch * BLK) * HD + h;
  const float* Bp = B + rowoff * ND;
  const float* Xp = X + rowoff * PD;
#pragma unroll
  for (int i = tid; i < 1024; i += 256) {
    const int l = i >> 4, cp = (i & 15) << 2;
    float4 bv = *(const float4*)&Bp[(size_t)l * HD * ND + cp];
    const float4 xv = *(const float4*)&Xp[(size_t)l * HD * PD + cp];
    const float d = s_dec[l];
    bv.x *= d; bv.y *= d; bv.z *= d; bv.w *= d;
    split4_store(sBh, sBl, l, cp, bv);
    split4_store(sXh, sXl, l, cp, xv);
  }
  __syncthreads();

  const int w = tid >> 5;
  const int r = w >> 1;            // n block (16 output rows)
  const int cb = (w & 1) * 2;      // first p block
  FragC acc[2];
  wmma::fill_fragment(acc[0], 0.f);
  wmma::fill_fragment(acc[1], 0.f);
#pragma unroll
  for (int k0 = 0; k0 < 4; k0++) {
    FragAC ah, al;  // Bdec^T: (n,l) at l*LDS_+n == col_major, ldm=LDS_
    wmma::load_matrix_sync(ah, &sBh[k0 * 16 * LDS_ + r * 16], LDS_);
    wmma::load_matrix_sync(al, &sBl[k0 * 16 * LDS_ + r * 16], LDS_);
#pragma unroll
    for (int ct = 0; ct < 2; ct++) {
      FragBR bh, bl;
      wmma::load_matrix_sync(bh, &sXh[k0 * 16 * LDS_ + (cb + ct) * 16], LDS_);
      wmma::load_matrix_sync(bl, &sXl[k0 * 16 * LDS_ + (cb + ct) * 16], LDS_);
      wmma::mma_sync(acc[ct], ah, bh, acc[ct]);
      wmma::mma_sync(acc[ct], ah, bl, acc[ct]);
      wmma::mma_sync(acc[ct], al, bh, acc[ct]);
    }
  }
  float* out = g_states + (((size_t)b * HD + h) * NCH + ch) * (size_t)(ND * PD);
#pragma unroll
  for (int ct = 0; ct < 2; ct++)
    wmma::store_matrix_sync(&out[(size_t)r * 16 * PD + (cb + ct) * 16], acc[ct],
                            PD, wmma::mem_row_major);
}

// ---------------------------------------------------------------------------
// K2: per (b,h): in-place scan over chunks (fp32, exact)
// ---------------------------------------------------------------------------
__global__ __launch_bounds__(256)
void k2_scan() {
  const int bh = blockIdx.x >> 3;
  const int seg = blockIdx.x & 7;
  __shared__ float dec[NCH];
  const int tid = threadIdx.x;
  if (tid < NCH) dec[tid] = expf(g_atot[(size_t)bh * NCH + tid]);
  __syncthreads();
  float* st = g_states + (size_t)bh * NCH * ND * PD + seg * 512 + tid;
  float run0 = 0.f, run1 = 0.f;
#pragma unroll 4
  for (int c = 0; c < NCH; c++) {
    const float d = dec[c];
    float t0 = st[0];
    float t1 = st[256];
    st[0] = run0;
    st[256] = run1;
    run0 = run0 * d + t0;
    run1 = run1 * d + t1;
    st += ND * PD;
  }
}

// ---------------------------------------------------------------------------
// K3: per (b,h,chunk):
//   GEMM1: Sraw = Cexp @ Bexp^T ;  tril mask + in-place split S over B tiles
//   GEMM2: Y = S @ X + Cexp @ SI
// smem (bf16 64x72 = 9216B each): Ch, Cl, Xh, Xl, SIh, SIl, Bh, Bl = 73728 B
//   After GEMM1: fp32 Sraw overlays Bh+Bl; then split S lands in-place:
//   Sh := Bh region, Sl := Bl region (register-staged to break the alias)
// ---------------------------------------------------------------------------
__global__ __launch_bounds__(256)
void k3_y(const float* __restrict__ A, const float* __restrict__ B,
          const float* __restrict__ C, const float* __restrict__ X,
          float* __restrict__ Y) {
  extern __shared__ char sm3[];
  __nv_bfloat16* sCh  = (__nv_bfloat16*)sm3;
  __nv_bfloat16* sCl  = sCh + 64 * LDS_;
  __nv_bfloat16* sXh  = sCl + 64 * LDS_;
  __nv_bfloat16* sXl  = sXh + 64 * LDS_;
  __nv_bfloat16* sSIh = sXl + 64 * LDS_;
  __nv_bfloat16* sSIl = sSIh + 64 * LDS_;
  __nv_bfloat16* sBh  = sSIl + 64 * LDS_;
  __nv_bfloat16* sBl  = sBh + 64 * LDS_;
  float* sSf = (float*)sBh;            // fp32 Sraw overlays Bh+Bl (18432 B)
  __nv_bfloat16* sSh = sBh;            // split S hi (in place)
  __nv_bfloat16* sSl = sBl;            // split S lo (in place)
  __shared__ float s_cum[BLK];
  __shared__ float s_rs[BLK], s_rsi[BLK];
  const int tid = threadIdx.x;
  const int ch = blockIdx.x, h = blockIdx.y, b = blockIdx.z;

  const float* Ap = A + ((size_t)b * SD + (size_t)ch * BLK) * HD + h;
  chunk_cumsum(Ap, s_cum, tid);
  if (tid < 64) { s_rs[tid] = expf(s_cum[tid]); s_rsi[tid] = expf(-s_cum[tid]); }
  __syncthreads();

  const size_t rowoff = ((size_t)b * SD + (size_t)ch * BLK) * HD + h;
  const float* Bp = B + rowoff * ND;
  const float* Cp = C + rowoff * ND;
  const float* Xp = X + rowoff * PD;
  const float* SIp = g_states + (((size_t)b * HD + h) * NCH + ch) * (size_t)(ND * PD);
#pragma unroll
  for (int i = tid; i < 1024; i += 256) {
    const int r = i >> 4, cp = (i & 15) << 2;
    float4 cv = *(const float4*)&Cp[(size_t)r * HD * ND + cp];
    float4 bv = *(const float4*)&Bp[(size_t)r * HD * ND + cp];
    const float4 xv = *(const float4*)&Xp[(size_t)r * HD * PD + cp];
    const float4 sv = *(const float4*)&SIp[(size_t)r * PD + cp];
    const float rs = s_rs[r], rsi = s_rsi[r];
    cv.x *= rs; cv.y *= rs; cv.z *= rs; cv.w *= rs;
    bv.x *= rsi; bv.y *= rsi; bv.z *= rsi; bv.w *= rsi;
    split4_store(sCh, sCl, r, cp, cv);
    split4_store(sBh, sBl, r, cp, bv);
    split4_store(sXh, sXl, r, cp, xv);
    split4_store(sSIh, sSIl, r, cp, sv);
  }
  __syncthreads();

  const int w = tid >> 5;
  const int r = w >> 1;        // i block
  const int cb = (w & 1) * 2;  // first j/p block

  // GEMM1: Sraw = Cexp @ Bexp^T
  {
    FragC acc[2];
    wmma::fill_fragment(acc[0], 0.f);
    wmma::fill_fragment(acc[1], 0.f);
#pragma unroll
    for (int k0 = 0; k0 < 4; k0++) {
      FragAR ah, al;
      wmma::load_matrix_sync(ah, &sCh[r * 16 * LDS_ + k0 * 16], LDS_);
      wmma::load_matrix_sync(al, &sCl[r * 16 * LDS_ + k0 * 16], LDS_);
#pragma unroll
      for (int ct = 0; ct < 2; ct++) {
        FragBC bh, bl;  // Bexp^T: col_major view of Bexp [j][n]
        wmma::load_matrix_sync(bh, &sBh[(cb + ct) * 16 * LDS_ + k0 * 16], LDS_);
        wmma::load_matrix_sync(bl, &sBl[(cb + ct) * 16 * LDS_ + k0 * 16], LDS_);
        wmma::mma_sync(acc[ct], ah, bh, acc[ct]);
        wmma::mma_sync(acc[ct], ah, bl, acc[ct]);
        wmma::mma_sync(acc[ct], al, bh, acc[ct]);
      }
    }
    __syncthreads();  // all warps done READING B tiles before fp32 overwrite
#pragma unroll
    for (int ct = 0; ct < 2; ct++)
      wmma::store_matrix_sync(&sSf[r * 16 * LDS_ + (cb + ct) * 16], acc[ct],
                              LDS_, wmma::mem_row_major);
  }
  __syncthreads();

  // tril mask + split S in place (stage fp32 in regs across the alias)
  {
    float2 v[8];
#pragma unroll
    for (int k = 0; k < 8; k++) {
      const int e = (tid + 256 * k) << 1;   // even element index
      const int i = e >> 6, j = e & 63;
      v[k].x = (j <= i) ? sSf[i * LDS_ + j] : 0.f;
      v[k].y = (j + 1 <= i) ? sSf[i * LDS_ + j + 1] : 0.f;
    }
    __syncthreads();
#pragma unroll
    for (int k = 0; k < 8; k++) {
      const int e = (tid + 256 * k) << 1;
      const int i = e >> 6, j = e & 63;
      __nv_bfloat16 h0, l0, h1, l1;
      bsplit(v[k].x, h0, l0);
      bsplit(v[k].y, h1, l1);
      *(uint32_t*)&sSh[i * LDS_ + j] = pk(h0, h1);
      *(uint32_t*)&sSl[i * LDS_ + j] = pk(l0, l1);
    }
  }
  __syncthreads();

  // GEMM2: Y = S @ X + Cexp @ SI  (fused accumulation)
  {
    FragC acc[2];
    wmma::fill_fragment(acc[0], 0.f);
    wmma::fill_fragment(acc[1], 0.f);
#pragma unroll
    for (int k0 = 0; k0 < 4; k0++) {
      FragAR sh, sl, chf, clf;
      wmma::load_matrix_sync(sh, &sSh[r * 16 * LDS_ + k0 * 16], LDS_);
      wmma::load_matrix_sync(sl, &sSl[r * 16 * LDS_ + k0 * 16], LDS_);
      wmma::load_matrix_sync(chf, &sCh[r * 16 * LDS_ + k0 * 16], LDS_);
      wmma::load_matrix_sync(clf, &sCl[r * 16 * LDS_ + k0 * 16], LDS_);
#pragma unroll
      for (int ct = 0; ct < 2; ct++) {
        FragBR xh, xl, ih, il;
        wmma::load_matrix_sync(xh, &sXh[k0 * 16 * LDS_ + (cb + ct) * 16], LDS_);
        wmma::load_matrix_sync(xl, &sXl[k0 * 16 * LDS_ + (cb + ct) * 16], LDS_);
        wmma::load_matrix_sync(ih, &sSIh[k0 * 16 * LDS_ + (cb + ct) * 16], LDS_);
        wmma::load_matrix_sync(il, &sSIl[k0 * 16 * LDS_ + (cb + ct) * 16], LDS_);
        wmma::mma_sync(acc[ct], sh, xh, acc[ct]);
        wmma::mma_sync(acc[ct], sh, xl, acc[ct]);
        wmma::mma_sync(acc[ct], sl, xh, acc[ct]);
        wmma::mma_sync(acc[ct], chf, ih, acc[ct]);
        wmma::mma_sync(acc[ct], chf, il, acc[ct]);
        wmma::mma_sync(acc[ct], clf, ih, acc[ct]);
      }
    }
    float* Yp = Y + rowoff * PD;
#pragma unroll
    for (int ct = 0; ct < 2; ct++)
      wmma::store_matrix_sync(&Yp[(size_t)r * 16 * HD * PD + (cb + ct) * 16],
                              acc[ct], HD * PD, wmma::mem_row_major);
  }
}

// ---------------------------------------------------------------------------
extern "C" void kernel_launch(void* const* d_in, const int* in_sizes, int n_in,
                              void* d_out, int out_size) {
  const float* X = (const float*)d_in[0];
  const float* A = (const float*)d_in[1];
  const float* B = (const float*)d_in[2];
  const float* C = (const float*)d_in[3];
  float* Y = (float*)d_out;

  const int smem_k1 = 4 * 64 * LDS_ * sizeof(__nv_bfloat16);  // 36864
  const int smem_k3 = 8 * 64 * LDS_ * sizeof(__nv_bfloat16);  // 73728
  cudaFuncSetAttribute(k1_states, cudaFuncAttributeMaxDynamicSharedMemorySize, smem_k1);
  cudaFuncSetAttribute(k3_y, cudaFuncAttributeMaxDynamicSharedMemorySize, smem_k3);

  dim3 grid(NCH, HD, BD);
  k1_states<<<grid, 256, smem_k1>>>(A, B, X);
  k2_scan<<<BD * HD * 8, 256>>>();
  k3_y<<<grid, 256, smem_k3>>>(A, B, C, X, Y);
}